// round 2
// baseline (speedup 1.0000x reference)
#include <cuda_runtime.h>
#include <cuda_fp16.h>
#include <cstdint>

// Problem constants
#define NE 8
#define NH 1024
#define NI 2048
#define NT 1024
#define MTILES 8          // NT / 128

#define BK 32
#define PAD 8
#define LDS_STRIDE (BK + PAD)   // 40 halves -> 80B row stride (8B aligned)

// ---------------- scratch (static device globals; no runtime alloc) ----------
__device__ int    g_cnt[NE];
__device__ int    g_tok[NE * NT];            // token | (kidx<<16)
__device__ float  g_wt [NE * NT];            // gate weight for that slot
__device__ __half g_act[(size_t)NE * NT * NI];   // 32 MB fp16 activations
__device__ float  g_y  [2 * NT * NH];        // 8 MB per-slot outputs

// ---------------- mma helper --------------------------------------------------
__device__ __forceinline__ void mma16816(float* c, const uint32_t* a,
                                         uint32_t b0, uint32_t b1) {
    asm volatile(
        "mma.sync.aligned.m16n8k16.row.col.f32.f16.f16.f32 "
        "{%0,%1,%2,%3}, {%4,%5,%6,%7}, {%8,%9}, {%0,%1,%2,%3};\n"
        : "+f"(c[0]), "+f"(c[1]), "+f"(c[2]), "+f"(c[3])
        : "r"(a[0]), "r"(a[1]), "r"(a[2]), "r"(a[3]), "r"(b0), "r"(b1));
}

// ---------------- router ------------------------------------------------------
__global__ void router_kernel(const float* __restrict__ logits) {
    int tid = threadIdx.x;
    if (tid < NE) g_cnt[tid] = 0;
    __syncthreads();
    for (int t = tid; t < NT; t += blockDim.x) {
        float l[NE];
#pragma unroll
        for (int e = 0; e < NE; e++) l[e] = logits[t * NE + e];
        int i1 = 0; float v1 = l[0];
#pragma unroll
        for (int e = 1; e < NE; e++) if (l[e] > v1) { v1 = l[e]; i1 = e; }
        int i2 = -1; float v2 = -1e30f;
#pragma unroll
        for (int e = 0; e < NE; e++) if (e != i1 && l[e] > v2) { v2 = l[e]; i2 = e; }
        float w1 = 1.f / (1.f + __expf(v2 - v1));
        float w2 = 1.f - w1;
        int p1 = atomicAdd(&g_cnt[i1], 1);
        g_tok[i1 * NT + p1] = t;              // kidx 0
        g_wt [i1 * NT + p1] = w1;
        int p2 = atomicAdd(&g_cnt[i2], 1);
        g_tok[i2 * NT + p2] = t | (1 << 16);  // kidx 1
        g_wt [i2 * NT + p2] = w2;
    }
}

// ---------------- GEMM1 + activation ------------------------------------------
// grid (NE*MTILES, NI/64). CTA: 128 gathered tokens x 64 cols of glu AND lin.
__global__ __launch_bounds__(256) void gemm1_kernel(
    const float* __restrict__ x, const float* __restrict__ w13,
    const float* __restrict__ b13)
{
    int e     = blockIdx.x >> 3;
    int mtile = blockIdx.x & 7;
    int cnt   = g_cnt[e];
    if (mtile * 128 >= cnt) return;
    int n0 = blockIdx.y * 64;

    __shared__ __align__(16) __half As[128 * LDS_STRIDE];
    __shared__ __align__(16) __half Bs[128 * LDS_STRIDE];
    __shared__ int stok[128];

    int tid = threadIdx.x;
    if (tid < 128) {
        int slot = mtile * 128 + tid;
        stok[tid] = (slot < cnt) ? (g_tok[e * NT + slot] & 0xFFFF) : 0;
    }
    __syncthreads();

    int warp = tid >> 5, lane = tid & 31;
    int wm = warp >> 1, wn = warp & 1;

    float acc[2][4][2][4];
#pragma unroll
    for (int h = 0; h < 2; h++)
#pragma unroll
        for (int j = 0; j < 4; j++)
#pragma unroll
            for (int mt = 0; mt < 2; mt++)
#pragma unroll
                for (int q = 0; q < 4; q++) acc[h][j][mt][q] = 0.f;

    const float* w13e = w13 + (size_t)e * (2 * NI) * NH;

    for (int k0 = 0; k0 < NH; k0 += BK) {
        __syncthreads();
        // load A: 128 rows x 32 halves (gathered x, fp32 -> fp16)
#pragma unroll
        for (int j = 0; j < 4; j++) {
            int idx = tid + j * 256;
            int row = idx >> 3, c4 = idx & 7;
            const float4 v = __ldg(reinterpret_cast<const float4*>(
                x + (size_t)stok[row] * NH + k0 + c4 * 4));
            __half2 h01 = __floats2half2_rn(v.x, v.y);
            __half2 h23 = __floats2half2_rn(v.z, v.w);
            *reinterpret_cast<__half2*>(&As[row * LDS_STRIDE + c4 * 4])     = h01;
            *reinterpret_cast<__half2*>(&As[row * LDS_STRIDE + c4 * 4 + 2]) = h23;
        }
        // load B: rows 0..63 = glu cols, 64..127 = lin cols
#pragma unroll
        for (int j = 0; j < 4; j++) {
            int idx = tid + j * 256;
            int row = idx >> 3, c4 = idx & 7;
            int wrow = (row < 64) ? (n0 + row) : (NI + n0 + row - 64);
            const float4 v = __ldg(reinterpret_cast<const float4*>(
                w13e + (size_t)wrow * NH + k0 + c4 * 4));
            __half2 h01 = __floats2half2_rn(v.x, v.y);
            __half2 h23 = __floats2half2_rn(v.z, v.w);
            *reinterpret_cast<__half2*>(&Bs[row * LDS_STRIDE + c4 * 4])     = h01;
            *reinterpret_cast<__half2*>(&Bs[row * LDS_STRIDE + c4 * 4 + 2]) = h23;
        }
        __syncthreads();

        const uint32_t* As32 = reinterpret_cast<const uint32_t*>(As);
        const uint32_t* Bs32 = reinterpret_cast<const uint32_t*>(Bs);
#pragma unroll
        for (int ks = 0; ks < 2; ks++) {
            int kb = ks * 16;
            uint32_t a[2][4];
#pragma unroll
            for (int mt = 0; mt < 2; mt++) {
                int r = wm * 32 + mt * 16 + (lane >> 2);
                int c = kb + (lane & 3) * 2;
                a[mt][0] = As32[r * 20 + (c >> 1)];
                a[mt][1] = As32[(r + 8) * 20 + (c >> 1)];
                a[mt][2] = As32[r * 20 + ((c + 8) >> 1)];
                a[mt][3] = As32[(r + 8) * 20 + ((c + 8) >> 1)];
            }
#pragma unroll
            for (int h = 0; h < 2; h++) {
#pragma unroll
                for (int j = 0; j < 4; j++) {
                    int n  = h * 64 + wn * 32 + j * 8 + (lane >> 2);
                    int ck = kb + (lane & 3) * 2;
                    uint32_t b0 = Bs32[n * 20 + (ck >> 1)];
                    uint32_t b1 = Bs32[n * 20 + ((ck + 8) >> 1)];
#pragma unroll
                    for (int mt = 0; mt < 2; mt++)
                        mma16816(acc[h][j][mt], a[mt], b0, b1);
                }
            }
        }
    }

    // epilogue: bias + gated activation, store fp16
    const float* b13e = b13 + (size_t)e * 2 * NI;
    size_t actbase = ((size_t)e * NT) * NI;
#pragma unroll
    for (int j = 0; j < 4; j++) {
#pragma unroll
        for (int mt = 0; mt < 2; mt++) {
#pragma unroll
            for (int q = 0; q < 4; q++) {
                int row  = wm * 32 + mt * 16 + (lane >> 2) + (q >> 1) * 8;
                int slot = mtile * 128 + row;
                if (slot >= cnt) continue;
                int col = n0 + wn * 32 + j * 8 + (lane & 3) * 2 + (q & 1);
                float gv = acc[0][j][mt][q] + b13e[col];
                float lv = acc[1][j][mt][q] + b13e[NI + col];
                float s  = 1.f / (1.f + __expf(-1.702f * gv));
                float av = gv * s * (lv + 1.f);
                g_act[actbase + (size_t)slot * NI + col] = __float2half(av);
            }
        }
    }
}

// ---------------- GEMM2 -------------------------------------------------------
// grid (NE*MTILES, NH/64). CTA: 128 slots x 64 output cols, K = NI.
__global__ __launch_bounds__(256) void gemm2_kernel(
    const float* __restrict__ w2, const float* __restrict__ b2)
{
    int e     = blockIdx.x >> 3;
    int mtile = blockIdx.x & 7;
    int cnt   = g_cnt[e];
    if (mtile * 128 >= cnt) return;
    int h0 = blockIdx.y * 64;

    __shared__ __align__(16) __half As[128 * LDS_STRIDE];
    __shared__ __align__(16) __half Bs[64 * LDS_STRIDE];
    __shared__ int   stok[128];
    __shared__ float swt [128];

    int tid = threadIdx.x;
    if (tid < 128) {
        int slot = mtile * 128 + tid;
        stok[tid] = (slot < cnt) ? g_tok[e * NT + slot] : -1;
        swt [tid] = (slot < cnt) ? g_wt [e * NT + slot] : 0.f;
    }
    __syncthreads();

    int warp = tid >> 5, lane = tid & 31;
    int wm = warp >> 1, wn = warp & 1;

    float acc[4][2][4];
#pragma unroll
    for (int j = 0; j < 4; j++)
#pragma unroll
        for (int mt = 0; mt < 2; mt++)
#pragma unroll
            for (int q = 0; q < 4; q++) acc[j][mt][q] = 0.f;

    const float* w2e = w2 + (size_t)e * NH * NI;
    size_t abase = ((size_t)e * NT + (size_t)mtile * 128) * NI;

    for (int k0 = 0; k0 < NI; k0 += BK) {
        __syncthreads();
        // A: 128 rows x 32 halves from fp16 scratch (no conversion)
#pragma unroll
        for (int j = 0; j < 4; j++) {
            int idx = tid + j * 256;
            int row = idx >> 3, c4 = idx & 7;
            const uint2 v = *reinterpret_cast<const uint2*>(
                g_act + abase + (size_t)row * NI + k0 + c4 * 4);
            *reinterpret_cast<uint2*>(&As[row * LDS_STRIDE + c4 * 4]) = v;
        }
        // B: 64 rows x 32 halves (w2 fp32 -> fp16)
#pragma unroll
        for (int j = 0; j < 2; j++) {
            int idx = tid + j * 256;
            int row = idx >> 3, c4 = idx & 7;
            const float4 v = __ldg(reinterpret_cast<const float4*>(
                w2e + (size_t)(h0 + row) * NI + k0 + c4 * 4));
            __half2 h01 = __floats2half2_rn(v.x, v.y);
            __half2 h23 = __floats2half2_rn(v.z, v.w);
            *reinterpret_cast<__half2*>(&Bs[row * LDS_STRIDE + c4 * 4])     = h01;
            *reinterpret_cast<__half2*>(&Bs[row * LDS_STRIDE + c4 * 4 + 2]) = h23;
        }
        __syncthreads();

        const uint32_t* As32 = reinterpret_cast<const uint32_t*>(As);
        const uint32_t* Bs32 = reinterpret_cast<const uint32_t*>(Bs);
#pragma unroll
        for (int ks = 0; ks < 2; ks++) {
            int kb = ks * 16;
            uint32_t a[2][4];
#pragma unroll
            for (int mt = 0; mt < 2; mt++) {
                int r = wm * 32 + mt * 16 + (lane >> 2);
                int c = kb + (lane & 3) * 2;
                a[mt][0] = As32[r * 20 + (c >> 1)];
                a[mt][1] = As32[(r + 8) * 20 + (c >> 1)];
                a[mt][2] = As32[r * 20 + ((c + 8) >> 1)];
                a[mt][3] = As32[(r + 8) * 20 + ((c + 8) >> 1)];
            }
#pragma unroll
            for (int j = 0; j < 4; j++) {
                int n  = wn * 32 + j * 8 + (lane >> 2);
                int ck = kb + (lane & 3) * 2;
                uint32_t b0 = Bs32[n * 20 + (ck >> 1)];
                uint32_t b1 = Bs32[n * 20 + ((ck + 8) >> 1)];
#pragma unroll
                for (int mt = 0; mt < 2; mt++)
                    mma16816(acc[j][mt], a[mt], b0, b1);
            }
        }
    }

    const float* b2e = b2 + (size_t)e * NH;
#pragma unroll
    for (int j = 0; j < 4; j++) {
#pragma unroll
        for (int mt = 0; mt < 2; mt++) {
#pragma unroll
            for (int q = 0; q < 4; q++) {
                int row  = wm * 32 + mt * 16 + (lane >> 2) + (q >> 1) * 8;
                int info = stok[row];
                if (info < 0) continue;
                int tok = info & 0xFFFF;
                int kid = (info >> 16) & 1;
                int col = h0 + wn * 32 + j * 8 + (lane & 3) * 2 + (q & 1);
                float val = acc[j][mt][q] + b2e[col];
                g_y[((size_t)kid * NT + tok) * NH + col] = swt[row] * val;
            }
        }
    }
}

// ---------------- final combine -----------------------------------------------
__global__ void combine_kernel(float* __restrict__ out) {
    int i = blockIdx.x * blockDim.x + threadIdx.x;
    if (i < NT * NH) out[i] = g_y[i] + g_y[NT * NH + i];
}

// ---------------- launch ------------------------------------------------------
extern "C" void kernel_launch(void* const* d_in, const int* in_sizes, int n_in,
                              void* d_out, int out_size) {
    const float* x      = (const float*)d_in[0];
    const float* logits = (const float*)d_in[1];
    const float* w13    = (const float*)d_in[2];
    const float* w2     = (const float*)d_in[3];
    const float* b13    = (const float*)d_in[4];
    const float* b2     = (const float*)d_in[5];
    float* out = (float*)d_out;

    router_kernel<<<1, 256>>>(logits);
    gemm1_kernel<<<dim3(NE * MTILES, NI / 64), 256>>>(x, w13, b13);
    gemm2_kernel<<<dim3(NE * MTILES, NH / 64), 256>>>(w2, b2);
    combine_kernel<<<(NT * NH + 255) / 256, 256>>>(out);
}

// round 6
// speedup vs baseline: 1.2485x; 1.2485x over previous
#include <cuda_runtime.h>
#include <cuda_fp16.h>
#include <cstdint>

// Problem constants
#define NE 8
#define NH 1024
#define NI 2048
#define NT 1024
#define MTILES 8

// CTA tile 128x128, K-stage 64 halves (128B rows), single-buffered smem,
// global-latency hidden by register prefetch of the next stage.
#define KSTAGE 64
#define TILEB  16384                       // 128 rows * 128 bytes

#define SW128(o) ((o) ^ (((o) >> 3) & 0x70))

// ---------------- scratch (static device globals) ----------------------------
__device__ int    g_cnt[NE];
__device__ int    g_tok[NE * NT];            // token | (kidx<<16)
__device__ float  g_wt [NE * NT];
__device__ __half g_act[(size_t)NE * NT * NI];   // 32 MB fp16 activations
__device__ float  g_y  [2 * NT * NH];            // 8 MB per-slot outputs

// ---------------- helpers -----------------------------------------------------
__device__ __forceinline__ uint32_t smem_u32(const void* p) {
    uint32_t a;
    asm("{ .reg .u64 t; cvta.to.shared.u64 t, %1; cvt.u32.u64 %0, t; }"
        : "=r"(a) : "l"(p));
    return a;
}
__device__ __forceinline__ void mma16816(float* c, const uint32_t* a,
                                         uint32_t b0, uint32_t b1) {
    asm volatile(
        "mma.sync.aligned.m16n8k16.row.col.f32.f16.f16.f32 "
        "{%0,%1,%2,%3}, {%4,%5,%6,%7}, {%8,%9}, {%0,%1,%2,%3};\n"
        : "+f"(c[0]), "+f"(c[1]), "+f"(c[2]), "+f"(c[3])
        : "r"(a[0]), "r"(a[1]), "r"(a[2]), "r"(a[3]), "r"(b0), "r"(b1));
}
__device__ __forceinline__ void ldsm4(uint32_t* r, uint32_t a) {
    asm volatile("ldmatrix.sync.aligned.m8n8.x4.shared.b16 {%0,%1,%2,%3}, [%4];"
                 : "=r"(r[0]), "=r"(r[1]), "=r"(r[2]), "=r"(r[3]) : "r"(a));
}
__device__ __forceinline__ uint32_t f2h(float a, float b) {
    __half2 h = __floats2half2_rn(a, b);
    return *reinterpret_cast<uint32_t*>(&h);
}
__device__ __forceinline__ uint4 cvt8(const float4& v0, const float4& v1) {
    return make_uint4(f2h(v0.x, v0.y), f2h(v0.z, v0.w),
                      f2h(v1.x, v1.y), f2h(v1.z, v1.w));
}

// ---------------- router ------------------------------------------------------
__global__ void router_kernel(const float* __restrict__ logits) {
    int tid = threadIdx.x;
    if (tid < NE) g_cnt[tid] = 0;
    __syncthreads();
    for (int t = tid; t < NT; t += blockDim.x) {
        float l[NE];
#pragma unroll
        for (int e = 0; e < NE; e++) l[e] = logits[t * NE + e];
        int i1 = 0; float v1 = l[0];
#pragma unroll
        for (int e = 1; e < NE; e++) if (l[e] > v1) { v1 = l[e]; i1 = e; }
        int i2 = -1; float v2 = -1e30f;
#pragma unroll
        for (int e = 0; e < NE; e++) if (e != i1 && l[e] > v2) { v2 = l[e]; i2 = e; }
        float w1 = 1.f / (1.f + __expf(v2 - v1));
        float w2 = 1.f - w1;
        int p1 = atomicAdd(&g_cnt[i1], 1);
        g_tok[i1 * NT + p1] = t;
        g_wt [i1 * NT + p1] = w1;
        int p2 = atomicAdd(&g_cnt[i2], 1);
        g_tok[i2 * NT + p2] = t | (1 << 16);
        g_wt [i2 * NT + p2] = w2;
    }
}

// ---------------- GEMM1: 128x128 HMMA, fused activation -----------------------
// grid (NE*MTILES, NI/64). D cols interleave glu/lin: col 2p=glu(n0+p), 2p+1=lin.
__global__ __launch_bounds__(512) void gemm1_kernel(
    const float* __restrict__ x, const float* __restrict__ w13,
    const float* __restrict__ b13)
{
    int e     = blockIdx.x >> 3;
    int mtile = blockIdx.x & 7;
    int cnt   = g_cnt[e];
    if (mtile * 128 >= cnt) return;
    int n0 = blockIdx.y * 64;          // pair base

    __shared__ __align__(128) char smA[TILEB];
    __shared__ __align__(128) char smB[TILEB];
    __shared__ int stok[128];

    int tid = threadIdx.x;
    uint32_t baseA = smem_u32(smA);
    uint32_t baseB = smem_u32(smB);

    if (tid < 128) {
        int slot = mtile * 128 + tid;
        stok[tid] = (slot < cnt) ? (g_tok[e * NT + slot] & 0xFFFF) : 0;
    }
    __syncthreads();

    // -------- load-thread mapping: r0 = tid>>3 in [0,64), rows r0 and r0+64
    int r0 = tid >> 3, c8 = tid & 7;
    const float* pA[2];
    const float* pB[2];
    {
        const float* w13e = w13 + (size_t)e * (2 * NI) * NH;
        pA[0] = x + (size_t)stok[r0]      * NH + c8 * 8;
        pA[1] = x + (size_t)stok[r0 + 64] * NH + c8 * 8;
#pragma unroll
        for (int p = 0; p < 2; p++) {
            int row = r0 + p * 64;
            int wrow = n0 + (row >> 1) + ((row & 1) ? NI : 0);
            pB[p] = w13e + (size_t)wrow * NH + c8 * 8;
        }
    }
    uint32_t sA[2], sB[2];
#pragma unroll
    for (int p = 0; p < 2; p++) {
        sA[p] = SW128((r0 + p * 64) * 128 + c8 * 16);
        sB[p] = SW128((r0 + p * 64) * 128 + c8 * 16);
    }

    // -------- mma-thread mapping
    int w = tid >> 5, lane = tid & 31;
    int wm = w & 3, wn = w >> 2;
    uint32_t a_off = (uint32_t)((wm * 32 + (lane & 15)) * 128 + (lane >> 4) * 16);
    uint32_t b_off = (uint32_t)((wn * 32 + (lane & 15)) * 128 + (lane >> 4) * 16);

    float acc[2][4][4];
#pragma unroll
    for (int mf = 0; mf < 2; mf++)
#pragma unroll
        for (int nf = 0; nf < 4; nf++)
#pragma unroll
            for (int q = 0; q < 4; q++) acc[mf][nf][q] = 0.f;

    const int S = NH / KSTAGE;   // 16
    float4 vA[2][2], vB[2][2];

#define LDG1(s) {                                                        \
        int k0 = (s) * KSTAGE;                                           \
        _Pragma("unroll")                                                \
        for (int p = 0; p < 2; p++) {                                    \
            vA[p][0] = __ldg((const float4*)(pA[p] + k0));               \
            vA[p][1] = __ldg((const float4*)(pA[p] + k0 + 4));           \
            vB[p][0] = __ldg((const float4*)(pB[p] + k0));               \
            vB[p][1] = __ldg((const float4*)(pB[p] + k0 + 4));           \
        } }
#define STS1() {                                                         \
        _Pragma("unroll")                                                \
        for (int p = 0; p < 2; p++) {                                    \
            *(uint4*)(smA + sA[p]) = cvt8(vA[p][0], vA[p][1]);           \
            *(uint4*)(smB + sB[p]) = cvt8(vB[p][0], vB[p][1]);           \
        } }

    LDG1(0); STS1(); __syncthreads();

    for (int s = 0; s < S; s++) {
        if (s + 1 < S) LDG1(s + 1);
#pragma unroll
        for (int ks = 0; ks < 4; ks++) {
            uint32_t kb = ks * 32;
            uint32_t af[2][4], bf[2][4];
            ldsm4(af[0], baseA + SW128(a_off + kb));
            ldsm4(af[1], baseA + SW128(a_off + 2048 + kb));
            ldsm4(bf[0], baseB + SW128(b_off + kb));
            ldsm4(bf[1], baseB + SW128(b_off + 2048 + kb));
#pragma unroll
            for (int mf = 0; mf < 2; mf++)
#pragma unroll
                for (int g = 0; g < 2; g++) {
                    mma16816(acc[mf][2 * g],     af[mf], bf[g][0], bf[g][2]);
                    mma16816(acc[mf][2 * g + 1], af[mf], bf[g][1], bf[g][3]);
                }
        }
        __syncthreads();
        if (s + 1 < S) { STS1(); __syncthreads(); }
    }

    // -------- epilogue: (c even, c odd) = (glu, lin) of one pair
    const float* b13e = b13 + (size_t)e * 2 * NI;
    size_t actbase = ((size_t)e * NT) * NI;
#pragma unroll
    for (int mf = 0; mf < 2; mf++) {
#pragma unroll
        for (int nf = 0; nf < 4; nf++) {
            int pc = n0 + wn * 16 + nf * 4 + (lane & 3);
            float bg = b13e[pc], bl = b13e[NI + pc];
#pragma unroll
            for (int h = 0; h < 2; h++) {
                int row  = wm * 32 + mf * 16 + (lane >> 2) + h * 8;
                int slot = mtile * 128 + row;
                if (slot >= cnt) continue;
                float gv = acc[mf][nf][2 * h]     + bg;
                float lv = acc[mf][nf][2 * h + 1] + bl;
                float sg = 1.f / (1.f + __expf(-1.702f * gv));
                float av = gv * sg * (lv + 1.f);
                g_act[actbase + (size_t)slot * NI + pc] = __float2half(av);
            }
        }
    }
}

// ---------------- GEMM2: 128x128 HMMA -----------------------------------------
// grid (NE*MTILES, NH/128).
__global__ __launch_bounds__(512) void gemm2_kernel(
    const float* __restrict__ w2, const float* __restrict__ b2)
{
    int e     = blockIdx.x >> 3;
    int mtile = blockIdx.x & 7;
    int cnt   = g_cnt[e];
    if (mtile * 128 >= cnt) return;
    int h0 = blockIdx.y * 128;

    __shared__ __align__(128) char smA[TILEB];
    __shared__ __align__(128) char smB[TILEB];
    __shared__ int   stok[128];
    __shared__ float swt [128];

    int tid = threadIdx.x;
    uint32_t baseA = smem_u32(smA);
    uint32_t baseB = smem_u32(smB);

    if (tid < 128) {
        int slot = mtile * 128 + tid;
        stok[tid] = (slot < cnt) ? g_tok[e * NT + slot] : -1;
        swt [tid] = (slot < cnt) ? g_wt [e * NT + slot] : 0.f;
    }
    __syncthreads();

    int r0 = tid >> 3, c8 = tid & 7;
    const __half* pA[2];
    const float*  pB[2];
    {
        const float* w2e = w2 + (size_t)e * NH * NI;
        size_t abase = ((size_t)e * NT + (size_t)mtile * 128) * NI;
#pragma unroll
        for (int p = 0; p < 2; p++) {
            pA[p] = g_act + abase + (size_t)(r0 + p * 64) * NI + c8 * 8;
            pB[p] = w2e + (size_t)(h0 + r0 + p * 64) * NI + c8 * 8;
        }
    }
    uint32_t sA[2], sB[2];
#pragma unroll
    for (int p = 0; p < 2; p++) {
        sA[p] = SW128((r0 + p * 64) * 128 + c8 * 16);
        sB[p] = SW128((r0 + p * 64) * 128 + c8 * 16);
    }

    int w = tid >> 5, lane = tid & 31;
    int wm = w & 3, wn = w >> 2;
    uint32_t a_off = (uint32_t)((wm * 32 + (lane & 15)) * 128 + (lane >> 4) * 16);
    uint32_t b_off = (uint32_t)((wn * 32 + (lane & 15)) * 128 + (lane >> 4) * 16);

    float acc[2][4][4];
#pragma unroll
    for (int mf = 0; mf < 2; mf++)
#pragma unroll
        for (int nf = 0; nf < 4; nf++)
#pragma unroll
            for (int q = 0; q < 4; q++) acc[mf][nf][q] = 0.f;

    const int S = NI / KSTAGE;   // 32
    uint4  vA[2];
    float4 vB[2][2];

#define LDG2(s) {                                                        \
        int k0 = (s) * KSTAGE;                                           \
        _Pragma("unroll")                                                \
        for (int p = 0; p < 2; p++) {                                    \
            vA[p]    = __ldg((const uint4*)(pA[p] + k0));                \
            vB[p][0] = __ldg((const float4*)(pB[p] + k0));               \
            vB[p][1] = __ldg((const float4*)(pB[p] + k0 + 4));           \
        } }
#define STS2() {                                                         \
        _Pragma("unroll")                                                \
        for (int p = 0; p < 2; p++) {                                    \
            *(uint4*)(smA + sA[p]) = vA[p];                              \
            *(uint4*)(smB + sB[p]) = cvt8(vB[p][0], vB[p][1]);           \
        } }

    LDG2(0); STS2(); __syncthreads();

    for (int s = 0; s < S; s++) {
        if (s + 1 < S) LDG2(s + 1);
#pragma unroll
        for (int ks = 0; ks < 4; ks++) {
            uint32_t kb = ks * 32;
            uint32_t af[2][4], bf[2][4];
            ldsm4(af[0], baseA + SW128(a_off + kb));
            ldsm4(af[1], baseA + SW128(a_off + 2048 + kb));
            ldsm4(bf[0], baseB + SW128(b_off + kb));
            ldsm4(bf[1], baseB + SW128(b_off + 2048 + kb));
#pragma unroll
            for (int mf = 0; mf < 2; mf++)
#pragma unroll
                for (int g = 0; g < 2; g++) {
                    mma16816(acc[mf][2 * g],     af[mf], bf[g][0], bf[g][2]);
                    mma16816(acc[mf][2 * g + 1], af[mf], bf[g][1], bf[g][3]);
                }
        }
        __syncthreads();
        if (s + 1 < S) { STS2(); __syncthreads(); }
    }

    const float* b2e = b2 + (size_t)e * NH;
#pragma unroll
    for (int mf = 0; mf < 2; mf++) {
#pragma unroll
        for (int h = 0; h < 2; h++) {
            int row  = wm * 32 + mf * 16 + (lane >> 2) + h * 8;
            int info = stok[row];
            if (info < 0) continue;
            int tok = info & 0xFFFF;
            int kid = (info >> 16) & 1;
            float wt = swt[row];
            float* dst = g_y + ((size_t)kid * NT + tok) * NH;
#pragma unroll
            for (int nf = 0; nf < 4; nf++) {
                int col = h0 + wn * 32 + nf * 8 + (lane & 3) * 2;
                float v0 = wt * (acc[mf][nf][2 * h]     + b2e[col]);
                float v1 = wt * (acc[mf][nf][2 * h + 1] + b2e[col + 1]);
                *(float2*)(dst + col) = make_float2(v0, v1);
            }
        }
    }
}

// ---------------- final combine -----------------------------------------------
__global__ void combine_kernel(float* __restrict__ out) {
    int i = blockIdx.x * blockDim.x + threadIdx.x;
    if (i < NT * NH) out[i] = g_y[i] + g_y[NT * NH + i];
}

// ---------------- launch ------------------------------------------------------
extern "C" void kernel_launch(void* const* d_in, const int* in_sizes, int n_in,
                              void* d_out, int out_size) {
    const float* x      = (const float*)d_in[0];
    const float* logits = (const float*)d_in[1];
    const float* w13    = (const float*)d_in[2];
    const float* w2     = (const float*)d_in[3];
    const float* b13    = (const float*)d_in[4];
    const float* b2     = (const float*)d_in[5];
    float* out = (float*)d_out;

    router_kernel<<<1, 256>>>(logits);
    gemm1_kernel<<<dim3(NE * MTILES, NI / 64), 512>>>(x, w13, b13);
    gemm2_kernel<<<dim3(NE * MTILES, NH / 128), 512>>>(w2, b2);
    combine_kernel<<<(NT * NH + 255) / 256, 256>>>(out);
}